// round 7
// baseline (speedup 1.0000x reference)
#include <cuda_runtime.h>
#include <cuda_fp16.h>
#include <cstdint>

#define BSZ 2
#define NQ 10000
#define EDIM 256
#define NH 8
#define NL 4
#define NP 8
#define DH 32
#define LEN_VAL 13294
#define NOA 768            // fused off(512) + attn(256) output width

// ---------------- scratch (device globals: allocation-free) ----------------
__device__ __half g_v16[(size_t)BSZ * LEN_VAL * EDIM];   // projected value (fp16)
__device__ __half g_a16[(size_t)BSZ * LEN_VAL * EDIM];   // raw value (fp16)
__device__ __half g_q16[(size_t)BSZ * NQ * EDIM];        // q = query + pos (fp16)
__device__ float  g_offattn[(size_t)BSZ * NQ * NOA];     // [off 512 | attn 256]
__device__ __half g_mid16[(size_t)BSZ * NQ * EDIM];      // sampling result (fp16)
__device__ float  g_bias_oa[NOA];

// fp16 weights [K][N], concatenated: [W_val 256x256][W_oa 256x768][W_out 256x256]
#define WOFF_VAL  0
#define WOFF_OA   65536
#define WOFF_OUT  262144
#define WTOTAL    327680
__device__ __half g_W16[WTOTAL];

#define N_VAL_ELEM (BSZ * LEN_VAL * EDIM)   // 6806528
#define N_Q_ELEM   (BSZ * NQ * EDIM)        // 5120000
#define PREP_TOTAL (N_VAL_ELEM + N_Q_ELEM + WTOTAL)

__constant__ int c_Hs[NL]    = {100, 50, 25, 13};
__constant__ int c_Ws[NL]    = {100, 50, 25, 13};
__constant__ int c_start[NL] = {0, 10000, 12500, 13125};

// ---------------- helpers ----------------
__device__ __forceinline__ void ldm_x4(uint32_t& r0, uint32_t& r1, uint32_t& r2, uint32_t& r3,
                                       uint32_t addr) {
    asm volatile("ldmatrix.sync.aligned.m8n8.x4.shared.b16 {%0,%1,%2,%3}, [%4];"
                 : "=r"(r0), "=r"(r1), "=r"(r2), "=r"(r3) : "r"(addr));
}

__device__ __forceinline__ void ldm_x4_trans(uint32_t& r0, uint32_t& r1, uint32_t& r2, uint32_t& r3,
                                             uint32_t addr) {
    asm volatile("ldmatrix.sync.aligned.m8n8.x4.trans.shared.b16 {%0,%1,%2,%3}, [%4];"
                 : "=r"(r0), "=r"(r1), "=r"(r2), "=r"(r3) : "r"(addr));
}

__device__ __forceinline__ void mma_f16(float* d, const uint32_t* a, const uint32_t* b) {
    asm volatile("mma.sync.aligned.m16n8k16.row.col.f32.f16.f16.f32 "
                 "{%0,%1,%2,%3},{%4,%5,%6,%7},{%8,%9},{%0,%1,%2,%3};"
                 : "+f"(d[0]), "+f"(d[1]), "+f"(d[2]), "+f"(d[3])
                 : "r"(a[0]), "r"(a[1]), "r"(a[2]), "r"(a[3]), "r"(b[0]), "r"(b[1]));
}

__device__ __forceinline__ void cp_async16(uint32_t dst, const void* src, bool pred) {
    int sz = pred ? 16 : 0;
    asm volatile("cp.async.cg.shared.global [%0], [%1], 16, %2;\n"
                 :: "r"(dst), "l"(src), "r"(sz));
}
#define CP_COMMIT() asm volatile("cp.async.commit_group;\n" ::)
#define CP_WAIT(N)  asm volatile("cp.async.wait_group %0;\n" :: "n"(N))

__device__ __forceinline__ void store2(float* p, float a, float b) {
    *(float2*)p = make_float2(a, b);
}
__device__ __forceinline__ void store2(__half* p, float a, float b) {
    *(__half2*)p = __floats2half2_rn(a, b);
}

// ---------------- fused prep kernel ----------------
// region 0: raw value -> fp16; region 1: q = query+pos -> fp16;
// region 2: weights -> fp16 (+ fused oa bias pack)
__global__ void prep_kernel(const float* __restrict__ value,
                            const float* __restrict__ query,
                            const float* __restrict__ qpos,
                            const float* __restrict__ W_val,
                            const float* __restrict__ W_off,
                            const float* __restrict__ W_attn,
                            const float* __restrict__ W_out,
                            const float* __restrict__ b_off,
                            const float* __restrict__ b_attn) {
    int i = blockIdx.x * blockDim.x + threadIdx.x;
    if (i < N_VAL_ELEM) {
        g_a16[i] = __float2half(value[i]);
    } else if (i < N_VAL_ELEM + N_Q_ELEM) {
        int j = i - N_VAL_ELEM;
        g_q16[j] = __float2half(query[j] + qpos[j]);
    } else if (i < PREP_TOTAL) {
        int j = i - N_VAL_ELEM - N_Q_ELEM;
        float x;
        if (j < WOFF_OA) {
            x = W_val[j];
        } else if (j < WOFF_OUT) {
            int k = j - WOFF_OA;
            int r = k / NOA, c = k - r * NOA;
            x = (c < 512) ? W_off[r * 512 + c] : W_attn[r * 256 + (c - 512)];
        } else {
            x = W_out[j - WOFF_OUT];
        }
        g_W16[j] = __float2half(x);
        if (j < NOA) g_bias_oa[j] = (j < 512) ? b_off[j] : b_attn[j - 512];
    }
}

// ---------------- fp16 tensor-core GEMM, cp.async 4-stage ----------------
// C[M,N] = A[M,256] @ B[256,N] + bias.  BM=128, BN=128, BK=32, 512 threads.
#define SA_STRIDE 40
#define SB_STRIDE 136
#define SA_BYTES  (128 * SA_STRIDE * 2)   // 10240
#define SB_BYTES  (32 * SB_STRIDE * 2)    // 8704
#define NSTAGE 4
#define OFF_A 0
#define OFF_B (NSTAGE * SA_BYTES)
#define GEMM_SMEM (NSTAGE * (SA_BYTES + SB_BYTES))   // 75776

template <typename TOut>
__global__ void __launch_bounds__(512, 1)
gemm_f16_kernel(const __half* __restrict__ A,
                const __half* __restrict__ B,
                const float* __restrict__ bias,
                TOut* __restrict__ C,
                int M, int N) {
    extern __shared__ char smem_raw[];
    const uint32_t sbase = (uint32_t)__cvta_generic_to_shared(smem_raw);

    const int tid  = threadIdx.x;
    const int lane = tid & 31;
    const int wid  = tid >> 5;
    const int warp_m = wid & 3;
    const int warp_n = wid >> 2;

    const int row0 = blockIdx.y * 128;
    const int col0 = blockIdx.x * 128;

    const int a_row = tid >> 2;           // 0..127
    const int a_c8  = (tid & 3) * 8;
    const int b_kr  = tid >> 4;           // 0..31
    const int b_c8  = (tid & 15) * 8;

    const bool a_pred = (row0 + a_row) < M;
    const __half* srcA = A + (size_t)(row0 + a_row) * 256 + a_c8;
    const __half* srcB = B + (size_t)b_kr * N + col0 + b_c8;

    const uint32_t dA = sbase + OFF_A + a_row * (SA_STRIDE * 2) + a_c8 * 2;
    const uint32_t dB = sbase + OFF_B + b_kr * (SB_STRIDE * 2) + b_c8 * 2;

#define ISSUE(J)                                                             \
    {                                                                        \
        int s = (J) & (NSTAGE - 1);                                          \
        int k0 = (J) * 32;                                                   \
        cp_async16(dA + s * SA_BYTES, srcA + k0, a_pred);                    \
        cp_async16(dB + s * SB_BYTES, srcB + (size_t)k0 * N, true);          \
    }

    ISSUE(0); CP_COMMIT();
    ISSUE(1); CP_COMMIT();
    ISSUE(2); CP_COMMIT();

    float acc[2][4][4];
#pragma unroll
    for (int mt = 0; mt < 2; mt++)
#pragma unroll
        for (int nb = 0; nb < 4; nb++)
#pragma unroll
            for (int j = 0; j < 4; j++) acc[mt][nb][j] = 0.f;

    const int NK = 8;
    for (int it = 0; it < NK; ++it) {
        CP_WAIT(2);
        __syncthreads();          // single barrier per k-iter: orders prior reads
        if (it + 3 < NK) ISSUE(it + 3);
        CP_COMMIT();

        const int s = it & (NSTAGE - 1);
        const uint32_t aB = sbase + OFF_A + s * SA_BYTES;
        const uint32_t bB = sbase + OFF_B + s * SB_BYTES;

#pragma unroll
        for (int ks = 0; ks < 2; ks++) {
            uint32_t af[2][4], bf[4][2];
#pragma unroll
            for (int mt = 0; mt < 2; mt++) {
                int row = warp_m * 32 + mt * 16 + (lane & 15);
                int col = ks * 16 + ((lane >> 4) << 3);
                ldm_x4(af[mt][0], af[mt][1], af[mt][2], af[mt][3],
                       aB + row * (SA_STRIDE * 2) + col * 2);
            }
#pragma unroll
            for (int g = 0; g < 2; g++) {
                int kk = ks * 16 + ((lane >> 3) & 1) * 8 + (lane & 7);
                int nn = warp_n * 32 + g * 16 + ((lane >> 4) & 1) * 8;
                uint32_t r0, r1, r2, r3;
                ldm_x4_trans(r0, r1, r2, r3, bB + kk * (SB_STRIDE * 2) + nn * 2);
                bf[2 * g][0] = r0;     bf[2 * g][1] = r1;
                bf[2 * g + 1][0] = r2; bf[2 * g + 1][1] = r3;
            }
#pragma unroll
            for (int mt = 0; mt < 2; mt++)
#pragma unroll
                for (int nb = 0; nb < 4; nb++)
                    mma_f16(acc[mt][nb], af[mt], bf[nb]);
        }
    }
#undef ISSUE

#pragma unroll
    for (int mt = 0; mt < 2; mt++) {
#pragma unroll
        for (int nb = 0; nb < 4; nb++) {
            int gn = col0 + warp_n * 32 + nb * 8 + (lane & 3) * 2;
            float b0 = bias[gn], b1 = bias[gn + 1];
            int gm0 = row0 + warp_m * 32 + mt * 16 + (lane >> 2);
            if (gm0 < M) store2(C + (size_t)gm0 * N + gn, acc[mt][nb][0] + b0, acc[mt][nb][1] + b1);
            int gm1 = gm0 + 8;
            if (gm1 < M) store2(C + (size_t)gm1 * N + gn, acc[mt][nb][2] + b0, acc[mt][nb][3] + b1);
        }
    }
}

// ---------------- deformable sampling (LDG.128 gather) ----------------
__global__ void __launch_bounds__(256)
sample_kernel(const float* __restrict__ ref) {
    __shared__ int4   s_ad[8][32];
    __shared__ float4 s_w[8][32];

    const int wlocal = threadIdx.x >> 5;
    const int lane   = threadIdx.x & 31;
    const int gw = blockIdx.x * 8 + wlocal;

    const int h = gw & (NH - 1);
    const int n = (gw >> 3) % NQ;
    const int b = gw / (NQ * NH);
    const long qrow = (long)b * NQ + n;
    const float* oa = g_offattn + qrow * NOA;

    // ---- phase 1 ----
    {
        int l = lane >> 3;
        int Hs = c_Hs[l], Ws = c_Ws[l];
        int ocol = ((h * NL + l) * NP + (lane & 7)) * 2;
        float ox = oa[ocol];
        float oy = oa[ocol + 1];
        float rx = ref[(qrow * NL + l) * 2 + 0];
        float ry = ref[(qrow * NL + l) * 2 + 1];

        float x = rx * (float)Ws + ox - 0.5f;
        float y = ry * (float)Hs + oy - 0.5f;

        float fx0 = floorf(x), fy0 = floorf(y);
        int x0 = (int)fx0, y0 = (int)fy0;
        float wx1 = x - fx0, wy1 = y - fy0;
        float wx0 = 1.f - wx1, wy0 = 1.f - wy1;

        float logit = oa[512 + h * DH + lane];
        float m = logit;
#pragma unroll
        for (int o = 16; o; o >>= 1) m = fmaxf(m, __shfl_xor_sync(0xFFFFFFFFu, m, o));
        float ex = __expf(logit - m);
        float s = ex;
#pragma unroll
        for (int o = 16; o; o >>= 1) s += __shfl_xor_sync(0xFFFFFFFFu, s, o);
        float aw = ex / s;

        int x1 = x0 + 1, y1 = y0 + 1;
        bool vx0 = (x0 >= 0) && (x0 < Ws);
        bool vx1 = (x1 >= 0) && (x1 < Ws);
        bool vy0 = (y0 >= 0) && (y0 < Hs);
        bool vy1 = (y1 >= 0) && (y1 < Hs);

        int base = (b * LEN_VAL + c_start[l]) * EDIM + h * DH;

        int p00 = (vy0 && vx0) ? (y0 * Ws + x0) : 0;
        int p01 = (vy0 && vx1) ? (y0 * Ws + x1) : 0;
        int p10 = (vy1 && vx0) ? (y1 * Ws + x0) : 0;
        int p11 = (vy1 && vx1) ? (y1 * Ws + x1) : 0;

        float w00 = (vy0 && vx0) ? aw * wx0 * wy0 : 0.f;
        float w01 = (vy0 && vx1) ? aw * wx1 * wy0 : 0.f;
        float w10 = (vy1 && vx0) ? aw * wx0 * wy1 : 0.f;
        float w11 = (vy1 && vx1) ? aw * wx1 * wy1 : 0.f;

        s_ad[wlocal][lane] = make_int4(base + p00 * EDIM, base + p01 * EDIM,
                                       base + p10 * EDIM, base + p11 * EDIM);
        s_w[wlocal][lane]  = make_float4(w00, w01, w10, w11);
    }
    __syncwarp();

    // ---- phase 2 ----
    const int slot = lane >> 2;    // 0..7 (sample slot)
    const int q4   = lane & 3;     // channel quad: halfs [8*q4, 8*q4+8)
    const __half* vb = g_v16;

    float2 acc[4];
#pragma unroll
    for (int j = 0; j < 4; j++) acc[j] = make_float2(0.f, 0.f);

#pragma unroll
    for (int it = 0; it < 4; it++) {
        int sIdx = it * 8 + slot;
        int4   ad = s_ad[wlocal][sIdx];
        float4 ww = s_w[wlocal][sIdx];
#pragma unroll
        for (int cn = 0; cn < 4; cn++) {
            int a = (cn == 0) ? ad.x : (cn == 1) ? ad.y : (cn == 2) ? ad.z : ad.w;
            float w = (cn == 0) ? ww.x : (cn == 1) ? ww.y : (cn == 2) ? ww.z : ww.w;
            uint4 u = *(const uint4*)(vb + a + q4 * 8);
            __half2 h0 = *(__half2*)&u.x;
            __half2 h1 = *(__half2*)&u.y;
            __half2 h2 = *(__half2*)&u.z;
            __half2 h3 = *(__half2*)&u.w;
            float2 f;
            f = __half22float2(h0); acc[0].x = fmaf(w, f.x, acc[0].x); acc[0].y = fmaf(w, f.y, acc[0].y);
            f = __half22float2(h1); acc[1].x = fmaf(w, f.x, acc[1].x); acc[1].y = fmaf(w, f.y, acc[1].y);
            f = __half22float2(h2); acc[2].x = fmaf(w, f.x, acc[2].x); acc[2].y = fmaf(w, f.y, acc[2].y);
            f = __half22float2(h3); acc[3].x = fmaf(w, f.x, acc[3].x); acc[3].y = fmaf(w, f.y, acc[3].y);
        }
    }

#pragma unroll
    for (int o = 4; o <= 16; o <<= 1) {
#pragma unroll
        for (int j = 0; j < 4; j++) {
            acc[j].x += __shfl_xor_sync(0xFFFFFFFFu, acc[j].x, o);
            acc[j].y += __shfl_xor_sync(0xFFFFFFFFu, acc[j].y, o);
        }
    }

    if (lane < 4) {
        __align__(16) __half2 outv[4];
#pragma unroll
        for (int j = 0; j < 4; j++) outv[j] = __floats2half2_rn(acc[j].x, acc[j].y);
        size_t midx = qrow * EDIM + h * DH + q4 * 8;
        *(uint4*)(g_mid16 + midx) = *(uint4*)outv;
    }
}

// ---------------- launch ----------------
extern "C" void kernel_launch(void* const* d_in, const int* in_sizes, int n_in,
                              void* d_out, int out_size) {
    const float* query   = (const float*)d_in[0];
    const float* value   = (const float*)d_in[1];
    const float* qpos    = (const float*)d_in[2];
    const float* refpts  = (const float*)d_in[3];
    const float* W_off   = (const float*)d_in[5];
    const float* b_off   = (const float*)d_in[6];
    const float* W_attn  = (const float*)d_in[7];
    const float* b_attn  = (const float*)d_in[8];
    const float* W_val   = (const float*)d_in[9];
    const float* b_val   = (const float*)d_in[10];
    const float* W_out   = (const float*)d_in[11];
    const float* b_out   = (const float*)d_in[12];
    float* out = (float*)d_out;

    __half *w16, *q16, *a16, *v16, *mid16;
    float *voa, *boa;
    cudaGetSymbolAddress((void**)&w16, g_W16);
    cudaGetSymbolAddress((void**)&q16, g_q16);
    cudaGetSymbolAddress((void**)&a16, g_a16);
    cudaGetSymbolAddress((void**)&v16, g_v16);
    cudaGetSymbolAddress((void**)&mid16, g_mid16);
    cudaGetSymbolAddress((void**)&voa, g_offattn);
    cudaGetSymbolAddress((void**)&boa, g_bias_oa);

    static bool init_done = false;
    static cudaStream_t s2;
    static cudaEvent_t evPrep, evVal;
    if (!init_done) {
        cudaFuncSetAttribute(gemm_f16_kernel<float>,
                             cudaFuncAttributeMaxDynamicSharedMemorySize, GEMM_SMEM);
        cudaFuncSetAttribute(gemm_f16_kernel<__half>,
                             cudaFuncAttributeMaxDynamicSharedMemorySize, GEMM_SMEM);
        cudaFuncSetAttribute(sample_kernel,
                             cudaFuncAttributePreferredSharedMemoryCarveout,
                             (int)cudaSharedmemCarveoutMaxL1);
        cudaStreamCreateWithFlags(&s2, cudaStreamNonBlocking);
        cudaEventCreateWithFlags(&evPrep, cudaEventDisableTiming);
        cudaEventCreateWithFlags(&evVal, cudaEventDisableTiming);
        init_done = true;
    }

    // 0) fused prep: value->fp16, q=query+pos->fp16, weights->fp16 (+bias pack)
    prep_kernel<<<(PREP_TOTAL + 255) / 256, 256>>>(
        value, query, qpos, W_val, W_off, W_attn, W_out, b_off, b_attn);

    // fork: value-projection chain on s2, offsets/attn chain on default stream
    cudaEventRecord(evPrep, 0);
    cudaStreamWaitEvent(s2, evPrep, 0);

    // 1a) [s2] v = value @ W_val + b_val -> fp16
    {
        int M = BSZ * LEN_VAL, N = EDIM;
        dim3 grid(N / 128, (M + 127) / 128);
        gemm_f16_kernel<__half><<<grid, 512, GEMM_SMEM, s2>>>(
            a16, w16 + WOFF_VAL, b_val, v16, M, N);
    }
    cudaEventRecord(evVal, s2);

    // 1b) [default] [off|attn] = q @ W_oa + b_oa (N = 768)
    {
        int M = BSZ * NQ, N = NOA;
        dim3 grid(N / 128, (M + 127) / 128);
        gemm_f16_kernel<float><<<grid, 512, GEMM_SMEM>>>(
            q16, w16 + WOFF_OA, boa, voa, M, N);
    }

    // join: sampling needs both v16 and offattn
    cudaStreamWaitEvent(0, evVal, 0);

    // 2) deformable sampling -> g_mid16
    {
        int groups = BSZ * NQ * NH;              // 160000
        sample_kernel<<<groups / 8, 256>>>(refpts);
    }
    // 3) out = mid @ W_out + b_out
    {
        int M = BSZ * NQ, N = EDIM;
        dim3 grid(N / 128, (M + 127) / 128);
        gemm_f16_kernel<float><<<grid, 512, GEMM_SMEM>>>(
            mid16, w16 + WOFF_OUT, b_out, out, M, N);
    }
}

// round 8
// speedup vs baseline: 2.2258x; 2.2258x over previous
#include <cuda_runtime.h>
#include <cuda_fp16.h>
#include <cstdint>

#define BSZ 2
#define NQ 10000
#define EDIM 256
#define NH 8
#define NL 4
#define NP 8
#define DH 32
#define LEN_VAL 13294
#define NOA 768            // fused off(512) + attn(256) output width

// ---------------- scratch (device globals: allocation-free) ----------------
__device__ __half g_v16[(size_t)BSZ * LEN_VAL * EDIM];   // projected value (fp16)
__device__ __half g_a16[(size_t)BSZ * LEN_VAL * EDIM];   // raw value (fp16)
__device__ __half g_q16[(size_t)BSZ * NQ * EDIM];        // q = query + pos (fp16)
__device__ float  g_offattn[(size_t)BSZ * NQ * NOA];     // [off 512 | attn 256]
__device__ __half g_mid16[(size_t)BSZ * NQ * EDIM];      // sampling result (fp16)
__device__ float  g_bias_oa[NOA];

// fp16 weights [K][N], concatenated: [W_val 256x256][W_oa 256x768][W_out 256x256]
#define WOFF_VAL  0
#define WOFF_OA   65536
#define WOFF_OUT  262144
#define WTOTAL    327680
__device__ __half g_W16[WTOTAL];

#define N_VAL_ELEM (BSZ * LEN_VAL * EDIM)   // 6806528
#define N_Q_ELEM   (BSZ * NQ * EDIM)        // 5120000
#define PREP_TOTAL (N_VAL_ELEM + N_Q_ELEM + WTOTAL)

__constant__ int c_Hs[NL]    = {100, 50, 25, 13};
__constant__ int c_Ws[NL]    = {100, 50, 25, 13};
__constant__ int c_start[NL] = {0, 10000, 12500, 13125};

// ---------------- helpers ----------------
__device__ __forceinline__ void ldm_x4(uint32_t& r0, uint32_t& r1, uint32_t& r2, uint32_t& r3,
                                       uint32_t addr) {
    asm volatile("ldmatrix.sync.aligned.m8n8.x4.shared.b16 {%0,%1,%2,%3}, [%4];"
                 : "=r"(r0), "=r"(r1), "=r"(r2), "=r"(r3) : "r"(addr));
}

__device__ __forceinline__ void ldm_x4_trans(uint32_t& r0, uint32_t& r1, uint32_t& r2, uint32_t& r3,
                                             uint32_t addr) {
    asm volatile("ldmatrix.sync.aligned.m8n8.x4.trans.shared.b16 {%0,%1,%2,%3}, [%4];"
                 : "=r"(r0), "=r"(r1), "=r"(r2), "=r"(r3) : "r"(addr));
}

__device__ __forceinline__ void mma_f16(float* d, const uint32_t* a, const uint32_t* b) {
    asm volatile("mma.sync.aligned.m16n8k16.row.col.f32.f16.f16.f32 "
                 "{%0,%1,%2,%3},{%4,%5,%6,%7},{%8,%9},{%0,%1,%2,%3};"
                 : "+f"(d[0]), "+f"(d[1]), "+f"(d[2]), "+f"(d[3])
                 : "r"(a[0]), "r"(a[1]), "r"(a[2]), "r"(a[3]), "r"(b[0]), "r"(b[1]));
}

__device__ __forceinline__ void cp_async16(uint32_t dst, const void* src, bool pred) {
    int sz = pred ? 16 : 0;
    asm volatile("cp.async.cg.shared.global [%0], [%1], 16, %2;\n"
                 :: "r"(dst), "l"(src), "r"(sz));
}
#define CP_COMMIT() asm volatile("cp.async.commit_group;\n" ::)
#define CP_WAIT(N)  asm volatile("cp.async.wait_group %0;\n" :: "n"(N))

__device__ __forceinline__ void store2(float* p, float a, float b) {
    *(float2*)p = make_float2(a, b);
}
__device__ __forceinline__ void store2(__half* p, float a, float b) {
    *(__half2*)p = __floats2half2_rn(a, b);
}

// ---------------- fused prep kernel ----------------
__global__ void prep_kernel(const float* __restrict__ value,
                            const float* __restrict__ query,
                            const float* __restrict__ qpos,
                            const float* __restrict__ W_val,
                            const float* __restrict__ W_off,
                            const float* __restrict__ W_attn,
                            const float* __restrict__ W_out,
                            const float* __restrict__ b_off,
                            const float* __restrict__ b_attn) {
    int i = blockIdx.x * blockDim.x + threadIdx.x;
    if (i < N_VAL_ELEM) {
        g_a16[i] = __float2half(value[i]);
    } else if (i < N_VAL_ELEM + N_Q_ELEM) {
        int j = i - N_VAL_ELEM;
        g_q16[j] = __float2half(query[j] + qpos[j]);
    } else if (i < PREP_TOTAL) {
        int j = i - N_VAL_ELEM - N_Q_ELEM;
        float x;
        if (j < WOFF_OA) {
            x = W_val[j];
        } else if (j < WOFF_OUT) {
            int k = j - WOFF_OA;
            int r = k / NOA, c = k - r * NOA;
            x = (c < 512) ? W_off[r * 512 + c] : W_attn[r * 256 + (c - 512)];
        } else {
            x = W_out[j - WOFF_OUT];
        }
        g_W16[j] = __float2half(x);
        if (j < NOA) g_bias_oa[j] = (j < 512) ? b_off[j] : b_attn[j - 512];
    }
}

// ---------------- fp16 tensor-core GEMM, cp.async 4-stage ----------------
#define SA_STRIDE 40
#define SB_STRIDE 136
#define SA_BYTES  (128 * SA_STRIDE * 2)   // 10240
#define SB_BYTES  (32 * SB_STRIDE * 2)    // 8704
#define NSTAGE 4
#define OFF_A 0
#define OFF_B (NSTAGE * SA_BYTES)
#define GEMM_SMEM (NSTAGE * (SA_BYTES + SB_BYTES))   // 75776

template <typename TOut>
__global__ void __launch_bounds__(512, 1)
gemm_f16_kernel(const __half* __restrict__ A,
                const __half* __restrict__ B,
                const float* __restrict__ bias,
                TOut* __restrict__ C,
                int M, int N) {
    extern __shared__ char smem_raw[];
    const uint32_t sbase = (uint32_t)__cvta_generic_to_shared(smem_raw);

    const int tid  = threadIdx.x;
    const int lane = tid & 31;
    const int wid  = tid >> 5;
    const int warp_m = wid & 3;
    const int warp_n = wid >> 2;

    const int row0 = blockIdx.y * 128;
    const int col0 = blockIdx.x * 128;

    const int a_row = tid >> 2;           // 0..127
    const int a_c8  = (tid & 3) * 8;
    const int b_kr  = tid >> 4;           // 0..31
    const int b_c8  = (tid & 15) * 8;

    const bool a_pred = (row0 + a_row) < M;
    const __half* srcA = A + (size_t)(row0 + a_row) * 256 + a_c8;
    const __half* srcB = B + (size_t)b_kr * N + col0 + b_c8;

    const uint32_t dA = sbase + OFF_A + a_row * (SA_STRIDE * 2) + a_c8 * 2;
    const uint32_t dB = sbase + OFF_B + b_kr * (SB_STRIDE * 2) + b_c8 * 2;

#define ISSUE(J)                                                             \
    {                                                                        \
        int s = (J) & (NSTAGE - 1);                                          \
        int k0 = (J) * 32;                                                   \
        cp_async16(dA + s * SA_BYTES, srcA + k0, a_pred);                    \
        cp_async16(dB + s * SB_BYTES, srcB + (size_t)k0 * N, true);          \
    }

    ISSUE(0); CP_COMMIT();
    ISSUE(1); CP_COMMIT();
    ISSUE(2); CP_COMMIT();

    float acc[2][4][4];
#pragma unroll
    for (int mt = 0; mt < 2; mt++)
#pragma unroll
        for (int nb = 0; nb < 4; nb++)
#pragma unroll
            for (int j = 0; j < 4; j++) acc[mt][nb][j] = 0.f;

    const int NK = 8;
    for (int it = 0; it < NK; ++it) {
        CP_WAIT(2);
        __syncthreads();          // single barrier per k-iter
        if (it + 3 < NK) ISSUE(it + 3);
        CP_COMMIT();

        const int s = it & (NSTAGE - 1);
        const uint32_t aB = sbase + OFF_A + s * SA_BYTES;
        const uint32_t bB = sbase + OFF_B + s * SB_BYTES;

#pragma unroll
        for (int ks = 0; ks < 2; ks++) {
            uint32_t af[2][4], bf[4][2];
#pragma unroll
            for (int mt = 0; mt < 2; mt++) {
                int row = warp_m * 32 + mt * 16 + (lane & 15);
                int col = ks * 16 + ((lane >> 4) << 3);
                ldm_x4(af[mt][0], af[mt][1], af[mt][2], af[mt][3],
                       aB + row * (SA_STRIDE * 2) + col * 2);
            }
#pragma unroll
            for (int g = 0; g < 2; g++) {
                int kk = ks * 16 + ((lane >> 3) & 1) * 8 + (lane & 7);
                int nn = warp_n * 32 + g * 16 + ((lane >> 4) & 1) * 8;
                uint32_t r0, r1, r2, r3;
                ldm_x4_trans(r0, r1, r2, r3, bB + kk * (SB_STRIDE * 2) + nn * 2);
                bf[2 * g][0] = r0;     bf[2 * g][1] = r1;
                bf[2 * g + 1][0] = r2; bf[2 * g + 1][1] = r3;
            }
#pragma unroll
            for (int mt = 0; mt < 2; mt++)
#pragma unroll
                for (int nb = 0; nb < 4; nb++)
                    mma_f16(acc[mt][nb], af[mt], bf[nb]);
        }
    }
#undef ISSUE

#pragma unroll
    for (int mt = 0; mt < 2; mt++) {
#pragma unroll
        for (int nb = 0; nb < 4; nb++) {
            int gn = col0 + warp_n * 32 + nb * 8 + (lane & 3) * 2;
            float b0 = bias[gn], b1 = bias[gn + 1];
            int gm0 = row0 + warp_m * 32 + mt * 16 + (lane >> 2);
            if (gm0 < M) store2(C + (size_t)gm0 * N + gn, acc[mt][nb][0] + b0, acc[mt][nb][1] + b1);
            int gm1 = gm0 + 8;
            if (gm1 < M) store2(C + (size_t)gm1 * N + gn, acc[mt][nb][2] + b0, acc[mt][nb][3] + b1);
        }
    }
}

// ---------------- deformable sampling (LDG.128 gather) ----------------
__global__ void __launch_bounds__(256)
sample_kernel(const float* __restrict__ ref) {
    __shared__ int4   s_ad[8][32];
    __shared__ float4 s_w[8][32];

    const int wlocal = threadIdx.x >> 5;
    const int lane   = threadIdx.x & 31;
    const int gw = blockIdx.x * 8 + wlocal;

    const int h = gw & (NH - 1);
    const int n = (gw >> 3) % NQ;
    const int b = gw / (NQ * NH);
    const long qrow = (long)b * NQ + n;
    const float* oa = g_offattn + qrow * NOA;

    // ---- phase 1 ----
    {
        int l = lane >> 3;
        int Hs = c_Hs[l], Ws = c_Ws[l];
        int ocol = ((h * NL + l) * NP + (lane & 7)) * 2;
        float ox = oa[ocol];
        float oy = oa[ocol + 1];
        float rx = ref[(qrow * NL + l) * 2 + 0];
        float ry = ref[(qrow * NL + l) * 2 + 1];

        float x = rx * (float)Ws + ox - 0.5f;
        float y = ry * (float)Hs + oy - 0.5f;

        float fx0 = floorf(x), fy0 = floorf(y);
        int x0 = (int)fx0, y0 = (int)fy0;
        float wx1 = x - fx0, wy1 = y - fy0;
        float wx0 = 1.f - wx1, wy0 = 1.f - wy1;

        float logit = oa[512 + h * DH + lane];
        float m = logit;
#pragma unroll
        for (int o = 16; o; o >>= 1) m = fmaxf(m, __shfl_xor_sync(0xFFFFFFFFu, m, o));
        float ex = __expf(logit - m);
        float s = ex;
#pragma unroll
        for (int o = 16; o; o >>= 1) s += __shfl_xor_sync(0xFFFFFFFFu, s, o);
        float aw = ex / s;

        int x1 = x0 + 1, y1 = y0 + 1;
        bool vx0 = (x0 >= 0) && (x0 < Ws);
        bool vx1 = (x1 >= 0) && (x1 < Ws);
        bool vy0 = (y0 >= 0) && (y0 < Hs);
        bool vy1 = (y1 >= 0) && (y1 < Hs);

        int base = (b * LEN_VAL + c_start[l]) * EDIM + h * DH;

        int p00 = (vy0 && vx0) ? (y0 * Ws + x0) : 0;
        int p01 = (vy0 && vx1) ? (y0 * Ws + x1) : 0;
        int p10 = (vy1 && vx0) ? (y1 * Ws + x0) : 0;
        int p11 = (vy1 && vx1) ? (y1 * Ws + x1) : 0;

        float w00 = (vy0 && vx0) ? aw * wx0 * wy0 : 0.f;
        float w01 = (vy0 && vx1) ? aw * wx1 * wy0 : 0.f;
        float w10 = (vy1 && vx0) ? aw * wx0 * wy1 : 0.f;
        float w11 = (vy1 && vx1) ? aw * wx1 * wy1 : 0.f;

        s_ad[wlocal][lane] = make_int4(base + p00 * EDIM, base + p01 * EDIM,
                                       base + p10 * EDIM, base + p11 * EDIM);
        s_w[wlocal][lane]  = make_float4(w00, w01, w10, w11);
    }
    __syncwarp();

    // ---- phase 2 ----
    const int slot = lane >> 2;    // 0..7 (sample slot)
    const int q4   = lane & 3;     // channel quad: halfs [8*q4, 8*q4+8)
    const __half* vb = g_v16;

    float2 acc[4];
#pragma unroll
    for (int j = 0; j < 4; j++) acc[j] = make_float2(0.f, 0.f);

#pragma unroll
    for (int it = 0; it < 4; it++) {
        int sIdx = it * 8 + slot;
        int4   ad = s_ad[wlocal][sIdx];
        float4 ww = s_w[wlocal][sIdx];
#pragma unroll
        for (int cn = 0; cn < 4; cn++) {
            int a = (cn == 0) ? ad.x : (cn == 1) ? ad.y : (cn == 2) ? ad.z : ad.w;
            float w = (cn == 0) ? ww.x : (cn == 1) ? ww.y : (cn == 2) ? ww.z : ww.w;
            uint4 u = *(const uint4*)(vb + a + q4 * 8);
            __half2 h0 = *(__half2*)&u.x;
            __half2 h1 = *(__half2*)&u.y;
            __half2 h2 = *(__half2*)&u.z;
            __half2 h3 = *(__half2*)&u.w;
            float2 f;
            f = __half22float2(h0); acc[0].x = fmaf(w, f.x, acc[0].x); acc[0].y = fmaf(w, f.y, acc[0].y);
            f = __half22float2(h1); acc[1].x = fmaf(w, f.x, acc[1].x); acc[1].y = fmaf(w, f.y, acc[1].y);
            f = __half22float2(h2); acc[2].x = fmaf(w, f.x, acc[2].x); acc[2].y = fmaf(w, f.y, acc[2].y);
            f = __half22float2(h3); acc[3].x = fmaf(w, f.x, acc[3].x); acc[3].y = fmaf(w, f.y, acc[3].y);
        }
    }

#pragma unroll
    for (int o = 4; o <= 16; o <<= 1) {
#pragma unroll
        for (int j = 0; j < 4; j++) {
            acc[j].x += __shfl_xor_sync(0xFFFFFFFFu, acc[j].x, o);
            acc[j].y += __shfl_xor_sync(0xFFFFFFFFu, acc[j].y, o);
        }
    }

    if (lane < 4) {
        __align__(16) __half2 outv[4];
#pragma unroll
        for (int j = 0; j < 4; j++) outv[j] = __floats2half2_rn(acc[j].x, acc[j].y);
        size_t midx = qrow * EDIM + h * DH + q4 * 8;
        *(uint4*)(g_mid16 + midx) = *(uint4*)outv;
    }
}

// ---------------- launch ----------------
extern "C" void kernel_launch(void* const* d_in, const int* in_sizes, int n_in,
                              void* d_out, int out_size) {
    const float* query   = (const float*)d_in[0];
    const float* value   = (const float*)d_in[1];
    const float* qpos    = (const float*)d_in[2];
    const float* refpts  = (const float*)d_in[3];
    const float* W_off   = (const float*)d_in[5];
    const float* b_off   = (const float*)d_in[6];
    const float* W_attn  = (const float*)d_in[7];
    const float* b_attn  = (const float*)d_in[8];
    const float* W_val   = (const float*)d_in[9];
    const float* b_val   = (const float*)d_in[10];
    const float* W_out   = (const float*)d_in[11];
    const float* b_out   = (const float*)d_in[12];
    float* out = (float*)d_out;

    __half *w16, *q16, *a16, *v16, *mid16;
    float *voa, *boa;
    cudaGetSymbolAddress((void**)&w16, g_W16);
    cudaGetSymbolAddress((void**)&q16, g_q16);
    cudaGetSymbolAddress((void**)&a16, g_a16);
    cudaGetSymbolAddress((void**)&v16, g_v16);
    cudaGetSymbolAddress((void**)&mid16, g_mid16);
    cudaGetSymbolAddress((void**)&voa, g_offattn);
    cudaGetSymbolAddress((void**)&boa, g_bias_oa);

    static bool init_done = false;
    static cudaStream_t s2;
    static cudaEvent_t evPrep, evVal;
    if (!init_done) {
        cudaFuncSetAttribute(gemm_f16_kernel<float>,
                             cudaFuncAttributeMaxDynamicSharedMemorySize, GEMM_SMEM);
        cudaFuncSetAttribute(gemm_f16_kernel<__half>,
                             cudaFuncAttributeMaxDynamicSharedMemorySize, GEMM_SMEM);
        cudaStreamCreateWithFlags(&s2, cudaStreamNonBlocking);
        cudaEventCreateWithFlags(&evPrep, cudaEventDisableTiming);
        cudaEventCreateWithFlags(&evVal, cudaEventDisableTiming);
        init_done = true;
    }

    // 0) fused prep
    prep_kernel<<<(PREP_TOTAL + 255) / 256, 256>>>(
        value, query, qpos, W_val, W_off, W_attn, W_out, b_off, b_attn);

    // fork: value-projection chain on s2
    cudaEventRecord(evPrep, 0);
    cudaStreamWaitEvent(s2, evPrep, 0);

    // 1a) [s2] v = value @ W_val + b_val -> fp16
    {
        int M = BSZ * LEN_VAL, N = EDIM;
        dim3 grid(N / 128, (M + 127) / 128);
        gemm_f16_kernel<__half><<<grid, 512, GEMM_SMEM, s2>>>(
            a16, w16 + WOFF_VAL, b_val, v16, M, N);
    }
    cudaEventRecord(evVal, s2);

    // 1b) [default] [off|attn] = q @ W_oa + b_oa (N = 768)
    {
        int M = BSZ * NQ, N = NOA;
        dim3 grid(N / 128, (M + 127) / 128);
        gemm_f16_kernel<float><<<grid, 512, GEMM_SMEM>>>(
            q16, w16 + WOFF_OA, boa, voa, M, N);
    }

    // join
    cudaStreamWaitEvent(0, evVal, 0);

    // 2) deformable sampling -> g_mid16
    {
        int groups = BSZ * NQ * NH;              // 160000
        sample_kernel<<<groups / 8, 256>>>(refpts);
    }
    // 3) out = mid @ W_out + b_out
    {
        int M = BSZ * NQ, N = EDIM;
        dim3 grid(N / 128, (M + 127) / 128);
        gemm_f16_kernel<float><<<grid, 512, GEMM_SMEM>>>(
            mid16, w16 + WOFF_OUT, b_out, out, M, N);
    }
}

// round 9
// speedup vs baseline: 2.3330x; 1.0482x over previous
#include <cuda_runtime.h>
#include <cuda_fp16.h>
#include <cstdint>

#define BSZ 2
#define NQ 10000
#define EDIM 256
#define NH 8
#define NL 4
#define NP 8
#define DH 32
#define LEN_VAL 13294
#define NOA 768            // fused off(512) + attn(256) output width

// ---------------- scratch (device globals: allocation-free) ----------------
// v16 layout: [b][h][pos][d] (d=32), +64 pad halfs for the x-pair overfetch
__device__ __half g_v16[(size_t)BSZ * NH * LEN_VAL * DH + 64];
__device__ __half g_a16[(size_t)BSZ * LEN_VAL * EDIM];   // raw value (fp16)
__device__ __half g_q16[(size_t)BSZ * NQ * EDIM];        // q = query + pos (fp16)
__device__ float  g_offattn[(size_t)BSZ * NQ * NOA];     // [off 512 | attn 256]
__device__ __half g_mid16[(size_t)BSZ * NQ * EDIM];      // sampling result (fp16)
__device__ float  g_bias_oa[NOA];

// fp16 weights [K][N], concatenated: [W_val 256x256][W_oa 256x768][W_out 256x256]
#define WOFF_VAL  0
#define WOFF_OA   65536
#define WOFF_OUT  262144
#define WTOTAL    327680
__device__ __half g_W16[WTOTAL];

#define N_VAL_ELEM (BSZ * LEN_VAL * EDIM)   // 6806528
#define N_Q_ELEM   (BSZ * NQ * EDIM)        // 5120000
#define PREP_TOTAL (N_VAL_ELEM + N_Q_ELEM + WTOTAL)

__constant__ int c_Hs[NL]    = {100, 50, 25, 13};
__constant__ int c_Ws[NL]    = {100, 50, 25, 13};
__constant__ int c_start[NL] = {0, 10000, 12500, 13125};

// ---------------- helpers ----------------
__device__ __forceinline__ void ldm_x4(uint32_t& r0, uint32_t& r1, uint32_t& r2, uint32_t& r3,
                                       uint32_t addr) {
    asm volatile("ldmatrix.sync.aligned.m8n8.x4.shared.b16 {%0,%1,%2,%3}, [%4];"
                 : "=r"(r0), "=r"(r1), "=r"(r2), "=r"(r3) : "r"(addr));
}

__device__ __forceinline__ void ldm_x4_trans(uint32_t& r0, uint32_t& r1, uint32_t& r2, uint32_t& r3,
                                             uint32_t addr) {
    asm volatile("ldmatrix.sync.aligned.m8n8.x4.trans.shared.b16 {%0,%1,%2,%3}, [%4];"
                 : "=r"(r0), "=r"(r1), "=r"(r2), "=r"(r3) : "r"(addr));
}

__device__ __forceinline__ void mma_f16(float* d, const uint32_t* a, const uint32_t* b) {
    asm volatile("mma.sync.aligned.m16n8k16.row.col.f32.f16.f16.f32 "
                 "{%0,%1,%2,%3},{%4,%5,%6,%7},{%8,%9},{%0,%1,%2,%3};"
                 : "+f"(d[0]), "+f"(d[1]), "+f"(d[2]), "+f"(d[3])
                 : "r"(a[0]), "r"(a[1]), "r"(a[2]), "r"(a[3]), "r"(b[0]), "r"(b[1]));
}

__device__ __forceinline__ void cp_async16(uint32_t dst, const void* src, bool pred) {
    int sz = pred ? 16 : 0;
    asm volatile("cp.async.cg.shared.global [%0], [%1], 16, %2;\n"
                 :: "r"(dst), "l"(src), "r"(sz));
}
#define CP_COMMIT() asm volatile("cp.async.commit_group;\n" ::)
#define CP_WAIT(N)  asm volatile("cp.async.wait_group %0;\n" :: "n"(N))

__device__ __forceinline__ void store2(float* p, float a, float b) {
    *(float2*)p = make_float2(a, b);
}
__device__ __forceinline__ void store2(__half* p, float a, float b) {
    *(__half2*)p = __floats2half2_rn(a, b);
}

// ---------------- fused prep kernel ----------------
__global__ void prep_kernel(const float* __restrict__ value,
                            const float* __restrict__ query,
                            const float* __restrict__ qpos,
                            const float* __restrict__ W_val,
                            const float* __restrict__ W_off,
                            const float* __restrict__ W_attn,
                            const float* __restrict__ W_out,
                            const float* __restrict__ b_off,
                            const float* __restrict__ b_attn) {
    int i = blockIdx.x * blockDim.x + threadIdx.x;
    if (i < N_VAL_ELEM) {
        g_a16[i] = __float2half(value[i]);
    } else if (i < N_VAL_ELEM + N_Q_ELEM) {
        int j = i - N_VAL_ELEM;
        g_q16[j] = __float2half(query[j] + qpos[j]);
    } else if (i < PREP_TOTAL) {
        int j = i - N_VAL_ELEM - N_Q_ELEM;
        float x;
        if (j < WOFF_OA) {
            x = W_val[j];
        } else if (j < WOFF_OUT) {
            int k = j - WOFF_OA;
            int r = k / NOA, c = k - r * NOA;
            x = (c < 512) ? W_off[r * 512 + c] : W_attn[r * 256 + (c - 512)];
        } else {
            x = W_out[j - WOFF_OUT];
        }
        g_W16[j] = __float2half(x);
        if (j < NOA) g_bias_oa[j] = (j < 512) ? b_off[j] : b_attn[j - 512];
    }
}

// ---------------- fp16 tensor-core GEMM, cp.async 4-stage ----------------
#define SA_STRIDE 40
#define SB_STRIDE 136
#define SA_BYTES  (128 * SA_STRIDE * 2)   // 10240
#define SB_BYTES  (32 * SB_STRIDE * 2)    // 8704
#define NSTAGE 4
#define OFF_A 0
#define OFF_B (NSTAGE * SA_BYTES)
#define GEMM_SMEM (NSTAGE * (SA_BYTES + SB_BYTES))   // 75776

// PERM=true: C is __half in [b][h][pos][d] layout (value projection)
template <typename TOut, bool PERM>
__global__ void __launch_bounds__(512, 1)
gemm_f16_kernel(const __half* __restrict__ A,
                const __half* __restrict__ B,
                const float* __restrict__ bias,
                TOut* __restrict__ C,
                int M, int N) {
    extern __shared__ char smem_raw[];
    const uint32_t sbase = (uint32_t)__cvta_generic_to_shared(smem_raw);

    const int tid  = threadIdx.x;
    const int lane = tid & 31;
    const int wid  = tid >> 5;
    const int warp_m = wid & 3;
    const int warp_n = wid >> 2;

    const int row0 = blockIdx.y * 128;
    const int col0 = blockIdx.x * 128;

    const int a_row = tid >> 2;           // 0..127
    const int a_c8  = (tid & 3) * 8;
    const int b_kr  = tid >> 4;           // 0..31
    const int b_c8  = (tid & 15) * 8;

    const bool a_pred = (row0 + a_row) < M;
    const __half* srcA = A + (size_t)(row0 + a_row) * 256 + a_c8;
    const __half* srcB = B + (size_t)b_kr * N + col0 + b_c8;

    const uint32_t dA = sbase + OFF_A + a_row * (SA_STRIDE * 2) + a_c8 * 2;
    const uint32_t dB = sbase + OFF_B + b_kr * (SB_STRIDE * 2) + b_c8 * 2;

#define ISSUE(J)                                                             \
    {                                                                        \
        int s = (J) & (NSTAGE - 1);                                          \
        int k0 = (J) * 32;                                                   \
        cp_async16(dA + s * SA_BYTES, srcA + k0, a_pred);                    \
        cp_async16(dB + s * SB_BYTES, srcB + (size_t)k0 * N, true);          \
    }

    ISSUE(0); CP_COMMIT();
    ISSUE(1); CP_COMMIT();
    ISSUE(2); CP_COMMIT();

    float acc[2][4][4];
#pragma unroll
    for (int mt = 0; mt < 2; mt++)
#pragma unroll
        for (int nb = 0; nb < 4; nb++)
#pragma unroll
            for (int j = 0; j < 4; j++) acc[mt][nb][j] = 0.f;

    const int NK = 8;
    for (int it = 0; it < NK; ++it) {
        CP_WAIT(2);
        __syncthreads();          // single barrier per k-iter
        if (it + 3 < NK) ISSUE(it + 3);
        CP_COMMIT();

        const int s = it & (NSTAGE - 1);
        const uint32_t aB = sbase + OFF_A + s * SA_BYTES;
        const uint32_t bB = sbase + OFF_B + s * SB_BYTES;

#pragma unroll
        for (int ks = 0; ks < 2; ks++) {
            uint32_t af[2][4], bf[4][2];
#pragma unroll
            for (int mt = 0; mt < 2; mt++) {
                int row = warp_m * 32 + mt * 16 + (lane & 15);
                int col = ks * 16 + ((lane >> 4) << 3);
                ldm_x4(af[mt][0], af[mt][1], af[mt][2], af[mt][3],
                       aB + row * (SA_STRIDE * 2) + col * 2);
            }
#pragma unroll
            for (int g = 0; g < 2; g++) {
                int kk = ks * 16 + ((lane >> 3) & 1) * 8 + (lane & 7);
                int nn = warp_n * 32 + g * 16 + ((lane >> 4) & 1) * 8;
                uint32_t r0, r1, r2, r3;
                ldm_x4_trans(r0, r1, r2, r3, bB + kk * (SB_STRIDE * 2) + nn * 2);
                bf[2 * g][0] = r0;     bf[2 * g][1] = r1;
                bf[2 * g + 1][0] = r2; bf[2 * g + 1][1] = r3;
            }
#pragma unroll
            for (int mt = 0; mt < 2; mt++)
#pragma unroll
                for (int nb = 0; nb < 4; nb++)
                    mma_f16(acc[mt][nb], af[mt], bf[nb]);
        }
    }
#undef ISSUE

#pragma unroll
    for (int mt = 0; mt < 2; mt++) {
#pragma unroll
        for (int nb = 0; nb < 4; nb++) {
            int gn = col0 + warp_n * 32 + nb * 8 + (lane & 3) * 2;
            float b0 = bias[gn], b1 = bias[gn + 1];
            int gm0 = row0 + warp_m * 32 + mt * 16 + (lane >> 2);
            int gm1 = gm0 + 8;
            if (PERM) {
                // dest: ((b*NH + h)*LEN_VAL + pos)*32 + d   (h = gn>>5, d = gn&31)
                int hh = gn >> 5, dd = gn & 31;
                if (gm0 < M) {
                    int bb = gm0 >= LEN_VAL;
                    int pos = gm0 - bb * LEN_VAL;
                    __half* dst = (__half*)C + ((size_t)(bb * NH + hh) * LEN_VAL + pos) * DH + dd;
                    store2(dst, acc[mt][nb][0] + b0, acc[mt][nb][1] + b1);
                }
                if (gm1 < M) {
                    int bb = gm1 >= LEN_VAL;
                    int pos = gm1 - bb * LEN_VAL;
                    __half* dst = (__half*)C + ((size_t)(bb * NH + hh) * LEN_VAL + pos) * DH + dd;
                    store2(dst, acc[mt][nb][2] + b0, acc[mt][nb][3] + b1);
                }
            } else {
                if (gm0 < M) store2(C + (size_t)gm0 * N + gn,
                                    acc[mt][nb][0] + b0, acc[mt][nb][1] + b1);
                if (gm1 < M) store2(C + (size_t)gm1 * N + gn,
                                    acc[mt][nb][2] + b0, acc[mt][nb][3] + b1);
            }
        }
    }
}

// ---------------- deformable sampling v4: head-major value + x-pair fetch ----------------
// Block = 256 threads = 8 warps, one warp per (b,n,h) group.
// Phase 1: lane i = sample i. Computes pair-start xb=clamp(x0,0,Ws-2), row addresses
//          for (y0,xb) and (y1,xb) in [b][h][pos][32] layout, and 4 folded weights
//          (wy0*wA, wy0*wB, wy1*wA, wy1*wB) where A/B are pixels xb, xb+1.
// Phase 2: 8 lanes per sample (4 samples in flight). Lane: half=(lane>>2)&1 picks
//          pixel A/B, q=lane&3 picks channels q*8..q*8+7. 2 LDG.128 per sample
//          (y0 row, y1 row). Reduce xor4 (A/B), xor8/16 (slots).
__global__ void __launch_bounds__(256)
sample_kernel(const float* __restrict__ ref) {
    __shared__ int2   s_ad[8][32];
    __shared__ float4 s_w[8][32];

    const int wlocal = threadIdx.x >> 5;
    const int lane   = threadIdx.x & 31;
    const int gw = blockIdx.x * 8 + wlocal;

    const int h = gw & (NH - 1);
    const int n = (gw >> 3) % NQ;
    const int b = gw / (NQ * NH);
    const long qrow = (long)b * NQ + n;
    const float* oa = g_offattn + qrow * NOA;

    // ---- phase 1 ----
    {
        int l = lane >> 3;
        int Hs = c_Hs[l], Ws = c_Ws[l];
        int ocol = ((h * NL + l) * NP + (lane & 7)) * 2;
        float ox = oa[ocol];
        float oy = oa[ocol + 1];
        float rx = ref[(qrow * NL + l) * 2 + 0];
        float ry = ref[(qrow * NL + l) * 2 + 1];

        float x = rx * (float)Ws + ox - 0.5f;
        float y = ry * (float)Hs + oy - 0.5f;

        float fx0 = floorf(x), fy0 = floorf(y);
        int x0 = (int)fx0, y0 = (int)fy0;
        float wx1 = x - fx0, wy1f = y - fy0;
        float wx0 = 1.f - wx1, wy0f = 1.f - wy1f;

        float logit = oa[512 + h * DH + lane];
        float m = logit;
#pragma unroll
        for (int o = 16; o; o >>= 1) m = fmaxf(m, __shfl_xor_sync(0xFFFFFFFFu, m, o));
        float ex = __expf(logit - m);
        float s = ex;
#pragma unroll
        for (int o = 16; o; o >>= 1) s += __shfl_xor_sync(0xFFFFFFFFu, s, o);
        float aw = ex / s;

        int x1 = x0 + 1, y1 = y0 + 1;
        bool vy0 = (y0 >= 0) && (y0 < Hs);
        bool vy1 = (y1 >= 0) && (y1 < Hs);

        // pair start + per-pixel x weights (zero when pixel isn't a valid corner)
        int xb = min(max(x0, 0), Ws - 2);
        int pA = xb, pB = xb + 1;
        float wxA = (pA == x0 ? wx0 : 0.f) + (pA == x1 ? wx1 : 0.f);
        float wxB = (pB == x0 ? wx0 : 0.f) + (pB == x1 ? wx1 : 0.f);

        float wy0 = vy0 ? aw * wy0f : 0.f;
        float wy1 = vy1 ? aw * wy1f : 0.f;
        int py0 = vy0 ? y0 : 0;
        int py1 = vy1 ? y1 : 0;

        // [b][h][pos][32] half-index of (py, xb)
        int base = ((b * NH + h) * LEN_VAL + c_start[l]) * DH;
        int a0 = base + (py0 * Ws + xb) * DH;
        int a1 = base + (py1 * Ws + xb) * DH;

        s_ad[wlocal][lane] = make_int2(a0, a1);
        s_w[wlocal][lane]  = make_float4(wy0 * wxA, wy0 * wxB, wy1 * wxA, wy1 * wxB);
    }
    __syncwarp();

    // ---- phase 2 ----
    const int slot = lane >> 3;          // 0..3 sample slot
    const int half = (lane >> 2) & 1;    // pixel A/B
    const int q    = lane & 3;           // channel quad (8 ch)
    const int sub  = half * DH + q * 8;  // half offset within 128B pair region
    const __half* vb = g_v16;

    float2 acc[4];
#pragma unroll
    for (int j = 0; j < 4; j++) acc[j] = make_float2(0.f, 0.f);

#pragma unroll
    for (int it = 0; it < 8; it++) {
        int sIdx = it * 4 + slot;
        int2   ad = s_ad[wlocal][sIdx];
        float4 ww = s_w[wlocal][sIdx];
        float w0 = half ? ww.y : ww.x;   // y0 row, this pixel
        float w1 = half ? ww.w : ww.z;   // y1 row, this pixel

        uint4 u0 = *(const uint4*)(vb + ad.x + sub);
        uint4 u1 = *(const uint4*)(vb + ad.y + sub);
        float2 f;
        f = __half22float2(*(__half2*)&u0.x); acc[0].x = fmaf(w0, f.x, acc[0].x); acc[0].y = fmaf(w0, f.y, acc[0].y);
        f = __half22float2(*(__half2*)&u0.y); acc[1].x = fmaf(w0, f.x, acc[1].x); acc[1].y = fmaf(w0, f.y, acc[1].y);
        f = __half22float2(*(__half2*)&u0.z); acc[2].x = fmaf(w0, f.x, acc[2].x); acc[2].y = fmaf(w0, f.y, acc[2].y);
        f = __half22float2(*(__half2*)&u0.w); acc[3].x = fmaf(w0, f.x, acc[3].x); acc[3].y = fmaf(w0, f.y, acc[3].y);
        f = __half22float2(*(__half2*)&u1.x); acc[0].x = fmaf(w1, f.x, acc[0].x); acc[0].y = fmaf(w1, f.y, acc[0].y);
        f = __half22float2(*(__half2*)&u1.y); acc[1].x = fmaf(w1, f.x, acc[1].x); acc[1].y = fmaf(w1, f.y, acc[1].y);
        f = __half22float2(*(__half2*)&u1.z); acc[2].x = fmaf(w1, f.x, acc[2].x); acc[2].y = fmaf(w1, f.y, acc[2].y);
        f = __half22float2(*(__half2*)&u1.w); acc[3].x = fmaf(w1, f.x, acc[3].x); acc[3].y = fmaf(w1, f.y, acc[3].y);
    }

    // reduce: xor4 combines pixel halves, xor8/16 combine sample slots
#pragma unroll
    for (int o = 4; o <= 16; o <<= 1) {
#pragma unroll
        for (int j = 0; j < 4; j++) {
            acc[j].x += __shfl_xor_sync(0xFFFFFFFFu, acc[j].x, o);
            acc[j].y += __shfl_xor_sync(0xFFFFFFFFu, acc[j].y, o);
        }
    }

    if (lane < 4) {   // lane == q
        __align__(16) __half2 outv[4];
#pragma unroll
        for (int j = 0; j < 4; j++) outv[j] = __floats2half2_rn(acc[j].x, acc[j].y);
        size_t midx = qrow * EDIM + h * DH + lane * 8;
        *(uint4*)(g_mid16 + midx) = *(uint4*)outv;
    }
}

// ---------------- launch ----------------
extern "C" void kernel_launch(void* const* d_in, const int* in_sizes, int n_in,
                              void* d_out, int out_size) {
    const float* query   = (const float*)d_in[0];
    const float* value   = (const float*)d_in[1];
    const float* qpos    = (const float*)d_in[2];
    const float* refpts  = (const float*)d_in[3];
    const float* W_off   = (const float*)d_in[5];
    const float* b_off   = (const float*)d_in[6];
    const float* W_attn  = (const float*)d_in[7];
    const float* b_attn  = (const float*)d_in[8];
    const float* W_val   = (const float*)d_in[9];
    const float* b_val   = (const float*)d_in[10];
    const float* W_out   = (const float*)d_in[11];
    const float* b_out   = (const float*)d_in[12];
    float* out = (float*)d_out;

    __half *w16, *q16, *a16, *v16, *mid16;
    float *voa, *boa;
    cudaGetSymbolAddress((void**)&w16, g_W16);
    cudaGetSymbolAddress((void**)&q16, g_q16);
    cudaGetSymbolAddress((void**)&a16, g_a16);
    cudaGetSymbolAddress((void**)&v16, g_v16);
    cudaGetSymbolAddress((void**)&mid16, g_mid16);
    cudaGetSymbolAddress((void**)&voa, g_offattn);
    cudaGetSymbolAddress((void**)&boa, g_bias_oa);

    static bool init_done = false;
    static cudaStream_t s2;
    static cudaEvent_t evPrep, evVal;
    if (!init_done) {
        cudaFuncSetAttribute((const void*)gemm_f16_kernel<float, false>,
                             cudaFuncAttributeMaxDynamicSharedMemorySize, GEMM_SMEM);
        cudaFuncSetAttribute((const void*)gemm_f16_kernel<__half, true>,
                             cudaFuncAttributeMaxDynamicSharedMemorySize, GEMM_SMEM);
        cudaStreamCreateWithFlags(&s2, cudaStreamNonBlocking);
        cudaEventCreateWithFlags(&evPrep, cudaEventDisableTiming);
        cudaEventCreateWithFlags(&evVal, cudaEventDisableTiming);
        init_done = true;
    }

    // 0) fused prep
    prep_kernel<<<(PREP_TOTAL + 255) / 256, 256>>>(
        value, query, qpos, W_val, W_off, W_attn, W_out, b_off, b_attn);

    // fork: value-projection chain on s2
    cudaEventRecord(evPrep, 0);
    cudaStreamWaitEvent(s2, evPrep, 0);

    // 1a) [s2] v = value @ W_val + b_val -> fp16 in [b][h][pos][d] layout
    {
        int M = BSZ * LEN_VAL, N = EDIM;
        dim3 grid(N / 128, (M + 127) / 128);
        gemm_f16_kernel<__half, true><<<grid, 512, GEMM_SMEM, s2>>>(
            a16, w16 + WOFF_VAL, b_val, v16, M, N);
    }
    cudaEventRecord(evVal, s2);

    // 1b) [default] [off|attn] = q @ W_oa + b_oa (N = 768)
    {
        int M = BSZ * NQ, N = NOA;
        dim3 grid(N / 128, (M + 127) / 128);
        gemm_f16_kernel<float, false><<<grid, 512, GEMM_SMEM>>>(
            q16, w16 + WOFF_OA, boa, voa, M, N);
    }

    // join
    cudaStreamWaitEvent(0, evVal, 0);

    // 2) deformable sampling -> g_mid16
    {
        int groups = BSZ * NQ * NH;              // 160000
        sample_kernel<<<groups / 8, 256>>>(refpts);
    }
    // 3) out = mid @ W_out + b_out
    {
        int M = BSZ * NQ, N = EDIM;
        dim3 grid(N / 128, (M + 127) / 128);
        gemm_f16_kernel<float, false><<<grid, 512, GEMM_SMEM>>>(
            mid16, w16 + WOFF_OUT, b_out, out, M, N);
    }
}

// round 10
// speedup vs baseline: 2.5863x; 1.1086x over previous
#include <cuda_runtime.h>
#include <cuda_fp16.h>
#include <cstdint>

#define BSZ 2
#define NQ 10000
#define EDIM 256
#define NH 8
#define NL 4
#define NP 8
#define DH 32
#define LEN_VAL 13294
#define NOA 768            // fused off(512) + attn(256) output width

// ---------------- scratch (device globals: allocation-free) ----------------
// v16 layout: [b][h][pos][d] (d=32), +64 pad halfs for the x-pair overfetch
__device__ __half g_v16[(size_t)BSZ * NH * LEN_VAL * DH + 64];
__device__ __half g_a16[(size_t)BSZ * LEN_VAL * EDIM];   // raw value (fp16)
__device__ __half g_q16[(size_t)BSZ * NQ * EDIM];        // q = query + pos (fp16)
__device__ float  g_offattn[(size_t)BSZ * NQ * NOA];     // [off 512 | attn 256]
__device__ __half g_mid16[(size_t)BSZ * NQ * EDIM];      // sampling result (fp16)
__device__ float  g_bias_oa[NOA];

// fp16 weights [K][N], concatenated: [W_val 256x256][W_oa 256x768][W_out 256x256]
#define WOFF_VAL  0
#define WOFF_OA   65536
#define WOFF_OUT  262144
#define WTOTAL    327680
__device__ __half g_W16[WTOTAL];

#define N_VAL_ELEM (BSZ * LEN_VAL * EDIM)   // 6806528
#define N_Q_ELEM   (BSZ * NQ * EDIM)        // 5120000
#define NV4 (N_VAL_ELEM / 4)
#define NQ4 (N_Q_ELEM / 4)
#define PREP_THREADS (NV4 + NQ4 + WTOTAL)

__constant__ int c_Hs[NL]    = {100, 50, 25, 13};
__constant__ int c_Ws[NL]    = {100, 50, 25, 13};
__constant__ int c_start[NL] = {0, 10000, 12500, 13125};

// ---------------- helpers ----------------
__device__ __forceinline__ void ldm_x4(uint32_t& r0, uint32_t& r1, uint32_t& r2, uint32_t& r3,
                                       uint32_t addr) {
    asm volatile("ldmatrix.sync.aligned.m8n8.x4.shared.b16 {%0,%1,%2,%3}, [%4];"
                 : "=r"(r0), "=r"(r1), "=r"(r2), "=r"(r3) : "r"(addr));
}

__device__ __forceinline__ void ldm_x4_trans(uint32_t& r0, uint32_t& r1, uint32_t& r2, uint32_t& r3,
                                             uint32_t addr) {
    asm volatile("ldmatrix.sync.aligned.m8n8.x4.trans.shared.b16 {%0,%1,%2,%3}, [%4];"
                 : "=r"(r0), "=r"(r1), "=r"(r2), "=r"(r3) : "r"(addr));
}

__device__ __forceinline__ void mma_f16(float* d, const uint32_t* a, const uint32_t* b) {
    asm volatile("mma.sync.aligned.m16n8k16.row.col.f32.f16.f16.f32 "
                 "{%0,%1,%2,%3},{%4,%5,%6,%7},{%8,%9},{%0,%1,%2,%3};"
                 : "+f"(d[0]), "+f"(d[1]), "+f"(d[2]), "+f"(d[3])
                 : "r"(a[0]), "r"(a[1]), "r"(a[2]), "r"(a[3]), "r"(b[0]), "r"(b[1]));
}

__device__ __forceinline__ void cp_async16(uint32_t dst, const void* src, bool pred) {
    int sz = pred ? 16 : 0;
    asm volatile("cp.async.cg.shared.global [%0], [%1], 16, %2;\n"
                 :: "r"(dst), "l"(src), "r"(sz));
}
#define CP_COMMIT() asm volatile("cp.async.commit_group;\n" ::)
#define CP_WAIT(N)  asm volatile("cp.async.wait_group %0;\n" :: "n"(N))

__device__ __forceinline__ void store2(float* p, float a, float b) {
    *(float2*)p = make_float2(a, b);
}
__device__ __forceinline__ void store2(__half* p, float a, float b) {
    *(__half2*)p = __floats2half2_rn(a, b);
}

// ---------------- fused prep kernel (vectorized) ----------------
__global__ void prep_kernel(const float4* __restrict__ value,
                            const float4* __restrict__ query,
                            const float4* __restrict__ qpos,
                            const float* __restrict__ W_val,
                            const float* __restrict__ W_off,
                            const float* __restrict__ W_attn,
                            const float* __restrict__ W_out,
                            const float* __restrict__ b_off,
                            const float* __restrict__ b_attn) {
    int i = blockIdx.x * blockDim.x + threadIdx.x;
    if (i < NV4) {
        float4 v = value[i];
        ((__half2*)g_a16)[i * 2]     = __floats2half2_rn(v.x, v.y);
        ((__half2*)g_a16)[i * 2 + 1] = __floats2half2_rn(v.z, v.w);
    } else if (i < NV4 + NQ4) {
        int j = i - NV4;
        float4 a = query[j], b = qpos[j];
        ((__half2*)g_q16)[j * 2]     = __floats2half2_rn(a.x + b.x, a.y + b.y);
        ((__half2*)g_q16)[j * 2 + 1] = __floats2half2_rn(a.z + b.z, a.w + b.w);
    } else if (i < PREP_THREADS) {
        int j = i - NV4 - NQ4;
        float x;
        if (j < WOFF_OA) {
            x = W_val[j];
        } else if (j < WOFF_OUT) {
            int k = j - WOFF_OA;
            int r = k / NOA, c = k - r * NOA;
            x = (c < 512) ? W_off[r * 512 + c] : W_attn[r * 256 + (c - 512)];
        } else {
            x = W_out[j - WOFF_OUT];
        }
        g_W16[j] = __float2half(x);
        if (j < NOA) g_bias_oa[j] = (j < 512) ? b_off[j] : b_attn[j - 512];
    }
}

// ---------------- fp16 tensor-core GEMM, cp.async 4-stage ----------------
// BM=128, BN=64, BK=32, 256 threads (8 warps 4x2, warp tile 32x32), 2 CTAs/SM.
#define SA_STRIDE 40
#define SB_STRIDE 72
#define SA_BYTES  (128 * SA_STRIDE * 2)   // 10240
#define SB_BYTES  (32 * SB_STRIDE * 2)    // 4608
#define NSTAGE 4
#define OFF_A 0
#define OFF_B (NSTAGE * SA_BYTES)
#define GEMM_SMEM (NSTAGE * (SA_BYTES + SB_BYTES))   // 59392

// PERM=true: C is __half in [b][h][pos][d] layout (value projection)
template <typename TOut, bool PERM>
__global__ void __launch_bounds__(256, 2)
gemm_f16_kernel(const __half* __restrict__ A,
                const __half* __restrict__ B,
                const float* __restrict__ bias,
                TOut* __restrict__ C,
                int M, int N) {
    extern __shared__ char smem_raw[];
    const uint32_t sbase = (uint32_t)__cvta_generic_to_shared(smem_raw);

    const int tid  = threadIdx.x;
    const int lane = tid & 31;
    const int wid  = tid >> 5;
    const int warp_m = wid & 3;       // 0..3
    const int warp_n = wid >> 2;      // 0..1

    const int row0 = blockIdx.y * 128;
    const int col0 = blockIdx.x * 64;

    // A: 128 rows x 32 halfs = 512 x 16B chunks, 2 per thread (adjacent)
    const int a_row = tid >> 1;             // 0..127
    const int a_c16 = (tid & 1) * 16;       // 0 or 16 halfs
    // B: 32 k-rows x 64 halfs = 256 x 16B chunks, 1 per thread
    const int b_kr  = tid >> 3;             // 0..31
    const int b_c8  = (tid & 7) * 8;        // 0..56

    const bool a_pred = (row0 + a_row) < M;
    const __half* srcA = A + (size_t)(row0 + a_row) * 256 + a_c16;
    const __half* srcB = B + (size_t)b_kr * N + col0 + b_c8;

    const uint32_t dA = sbase + OFF_A + a_row * (SA_STRIDE * 2) + a_c16 * 2;
    const uint32_t dB = sbase + OFF_B + b_kr * (SB_STRIDE * 2) + b_c8 * 2;

#define ISSUE(J)                                                             \
    {                                                                        \
        int s = (J) & (NSTAGE - 1);                                          \
        int k0 = (J) * 32;                                                   \
        cp_async16(dA + s * SA_BYTES, srcA + k0, a_pred);                    \
        cp_async16(dA + s * SA_BYTES + 16, srcA + k0 + 8, a_pred);           \
        cp_async16(dB + s * SB_BYTES, srcB + (size_t)k0 * N, true);          \
    }

    ISSUE(0); CP_COMMIT();
    ISSUE(1); CP_COMMIT();
    ISSUE(2); CP_COMMIT();

    float acc[2][4][4];
#pragma unroll
    for (int mt = 0; mt < 2; mt++)
#pragma unroll
        for (int nb = 0; nb < 4; nb++)
#pragma unroll
            for (int j = 0; j < 4; j++) acc[mt][nb][j] = 0.f;

    const int NK = 8;
    for (int it = 0; it < NK; ++it) {
        CP_WAIT(2);
        __syncthreads();          // single barrier per k-iter
        if (it + 3 < NK) ISSUE(it + 3);
        CP_COMMIT();

        const int s = it & (NSTAGE - 1);
        const uint32_t aB = sbase + OFF_A + s * SA_BYTES;
        const uint32_t bB = sbase + OFF_B + s * SB_BYTES;

#pragma unroll
        for (int ks = 0; ks < 2; ks++) {
            uint32_t af[2][4], bf[4][2];
#pragma unroll
            for (int mt = 0; mt < 2; mt++) {
                int row = warp_m * 32 + mt * 16 + (lane & 15);
                int col = ks * 16 + ((lane >> 4) << 3);
                ldm_x4(af[mt][0], af[mt][1], af[mt][2], af[mt][3],
                       aB + row * (SA_STRIDE * 2) + col * 2);
            }
#pragma unroll
            for (int g = 0; g < 2; g++) {
                int kk = ks * 16 + ((lane >> 3) & 1) * 8 + (lane & 7);
                int nn = warp_n * 32 + g * 16 + ((lane >> 4) & 1) * 8;
                uint32_t r0, r1, r2, r3;
                ldm_x4_trans(r0, r1, r2, r3, bB + kk * (SB_STRIDE * 2) + nn * 2);
                bf[2 * g][0] = r0;     bf[2 * g][1] = r1;
                bf[2 * g + 1][0] = r2; bf[2 * g + 1][1] = r3;
            }
#pragma unroll
            for (int mt = 0; mt < 2; mt++)
#pragma unroll
                for (int nb = 0; nb < 4; nb++)
                    mma_f16(acc[mt][nb], af[mt], bf[nb]);
        }
    }
#undef ISSUE

#pragma unroll
    for (int mt = 0; mt < 2; mt++) {
#pragma unroll
        for (int nb = 0; nb < 4; nb++) {
            int gn = col0 + warp_n * 32 + nb * 8 + (lane & 3) * 2;
            float b0 = bias[gn], b1 = bias[gn + 1];
            int gm0 = row0 + warp_m * 32 + mt * 16 + (lane >> 2);
            int gm1 = gm0 + 8;
            if (PERM) {
                int hh = gn >> 5, dd = gn & 31;
                if (gm0 < M) {
                    int bb = gm0 >= LEN_VAL;
                    int pos = gm0 - bb * LEN_VAL;
                    __half* dst = (__half*)C + ((size_t)(bb * NH + hh) * LEN_VAL + pos) * DH + dd;
                    store2(dst, acc[mt][nb][0] + b0, acc[mt][nb][1] + b1);
                }
                if (gm1 < M) {
                    int bb = gm1 >= LEN_VAL;
                    int pos = gm1 - bb * LEN_VAL;
                    __half* dst = (__half*)C + ((size_t)(bb * NH + hh) * LEN_VAL + pos) * DH + dd;
                    store2(dst, acc[mt][nb][2] + b0, acc[mt][nb][3] + b1);
                }
            } else {
                if (gm0 < M) store2(C + (size_t)gm0 * N + gn,
                                    acc[mt][nb][0] + b0, acc[mt][nb][1] + b1);
                if (gm1 < M) store2(C + (size_t)gm1 * N + gn,
                                    acc[mt][nb][2] + b0, acc[mt][nb][3] + b1);
            }
        }
    }
}

// ---------------- deformable sampling v4 (unchanged from R9) ----------------
__global__ void __launch_bounds__(256)
sample_kernel(const float* __restrict__ ref) {
    __shared__ int2   s_ad[8][32];
    __shared__ float4 s_w[8][32];

    const int wlocal = threadIdx.x >> 5;
    const int lane   = threadIdx.x & 31;
    const int gw = blockIdx.x * 8 + wlocal;

    const int h = gw & (NH - 1);
    const int n = (gw >> 3) % NQ;
    const int b = gw / (NQ * NH);
    const long qrow = (long)b * NQ + n;
    const float* oa = g_offattn + qrow * NOA;

    // ---- phase 1 ----
    {
        int l = lane >> 3;
        int Hs = c_Hs[l], Ws = c_Ws[l];
        int ocol = ((h * NL + l) * NP + (lane & 7)) * 2;
        float ox = oa[ocol];
        float oy = oa[ocol + 1];
        float rx = ref[(qrow * NL + l) * 2 + 0];
        float ry = ref[(qrow * NL + l) * 2 + 1];

        float x = rx * (float)Ws + ox - 0.5f;
        float y = ry * (float)Hs + oy - 0.5f;

        float fx0 = floorf(x), fy0 = floorf(y);
        int x0 = (int)fx0, y0 = (int)fy0;
        float wx1 = x - fx0, wy1f = y - fy0;
        float wx0 = 1.f - wx1, wy0f = 1.f - wy1f;

        float logit = oa[512 + h * DH + lane];
        float m = logit;
#pragma unroll
        for (int o = 16; o; o >>= 1) m = fmaxf(m, __shfl_xor_sync(0xFFFFFFFFu, m, o));
        float ex = __expf(logit - m);
        float s = ex;
#pragma unroll
        for (int o = 16; o; o >>= 1) s += __shfl_xor_sync(0xFFFFFFFFu, s, o);
        float aw = ex / s;

        int x1 = x0 + 1, y1 = y0 + 1;
        bool vy0 = (y0 >= 0) && (y0 < Hs);
        bool vy1 = (y1 >= 0) && (y1 < Hs);

        int xb = min(max(x0, 0), Ws - 2);
        int pA = xb, pB = xb + 1;
        float wxA = (pA == x0 ? wx0 : 0.f) + (pA == x1 ? wx1 : 0.f);
        float wxB = (pB == x0 ? wx0 : 0.f) + (pB == x1 ? wx1 : 0.f);

        float wy0 = vy0 ? aw * wy0f : 0.f;
        float wy1 = vy1 ? aw * wy1f : 0.f;
        int py0 = vy0 ? y0 : 0;
        int py1 = vy1 ? y1 : 0;

        int base = ((b * NH + h) * LEN_VAL + c_start[l]) * DH;
        int a0 = base + (py0 * Ws + xb) * DH;
        int a1 = base + (py1 * Ws + xb) * DH;

        s_ad[wlocal][lane] = make_int2(a0, a1);
        s_w[wlocal][lane]  = make_float4(wy0 * wxA, wy0 * wxB, wy1 * wxA, wy1 * wxB);
    }
    __syncwarp();

    // ---- phase 2 ----
    const int slot = lane >> 3;          // 0..3 sample slot
    const int half = (lane >> 2) & 1;    // pixel A/B
    const int q    = lane & 3;           // channel quad (8 ch)
    const int sub  = half * DH + q * 8;
    const __half* vb = g_v16;

    float2 acc[4];
#pragma unroll
    for (int j = 0; j < 4; j++) acc[j] = make_float2(0.f, 0.f);

#pragma unroll
    for (int it = 0; it < 8; it++) {
        int sIdx = it * 4 + slot;
        int2   ad = s_ad[wlocal][sIdx];
        float4 ww = s_w[wlocal][sIdx];
        float w0 = half ? ww.y : ww.x;
        float w1 = half ? ww.w : ww.z;

        uint4 u0 = *(const uint4*)(vb + ad.x + sub);
        uint4 u1 = *(const uint4*)(vb + ad.y + sub);
        float2 f;
        f = __half22float2(*(__half2*)&u0.x); acc[0].x = fmaf(w0, f.x, acc[0].x); acc[0].y = fmaf(w0, f.y, acc[0].y);
        f = __half22float2(*(__half2*)&u0.y); acc[1].x = fmaf(w0, f.x, acc[1].x); acc[1].y = fmaf(w0, f.y, acc[1].y);
        f = __half22float2(*(__half2*)&u0.z); acc[2].x = fmaf(w0, f.x, acc[2].x); acc[2].y = fmaf(w0, f.y, acc[2].y);
        f = __half22float2(*(__half2*)&u0.w); acc[3].x = fmaf(w0, f.x, acc[3].x); acc[3].y = fmaf(w0, f.y, acc[3].y);
        f = __half22float2(*(__half2*)&u1.x); acc[0].x = fmaf(w1, f.x, acc[0].x); acc[0].y = fmaf(w1, f.y, acc[0].y);
        f = __half22float2(*(__half2*)&u1.y); acc[1].x = fmaf(w1, f.x, acc[1].x); acc[1].y = fmaf(w1, f.y, acc[1].y);
        f = __half22float2(*(__half2*)&u1.z); acc[2].x = fmaf(w1, f.x, acc[2].x); acc[2].y = fmaf(w1, f.y, acc[2].y);
        f = __half22float2(*(__half2*)&u1.w); acc[3].x = fmaf(w1, f.x, acc[3].x); acc[3].y = fmaf(w1, f.y, acc[3].y);
    }

#pragma unroll
    for (int o = 4; o <= 16; o <<= 1) {
#pragma unroll
        for (int j = 0; j < 4; j++) {
            acc[j].x += __shfl_xor_sync(0xFFFFFFFFu, acc[j].x, o);
            acc[j].y += __shfl_xor_sync(0xFFFFFFFFu, acc[j].y, o);
        }
    }

    if (lane < 4) {
        __align__(16) __half2 outv[4];
#pragma unroll
        for (int j = 0; j < 4; j++) outv[j] = __floats2half2_rn(acc[j].x, acc[j].y);
        size_t midx = qrow * EDIM + h * DH + lane * 8;
        *(uint4*)(g_mid16 + midx) = *(uint4*)outv;
    }
}

// ---------------- launch ----------------
extern "C" void kernel_launch(void* const* d_in, const int* in_sizes, int n_in,
                              void* d_out, int out_size) {
    const float* query   = (const float*)d_in[0];
    const float* value   = (const float*)d_in[1];
    const float* qpos    = (const float*)d_in[2];
    const float* refpts  = (const float*)d_in[3];
    const float* W_off   = (const float*)d_in[5];
    const float* b_off   = (const float*)d_in[6];
    const float* W_attn  = (const float*)d_in[7];
    const float* b_attn  = (const float*)d_in[8];
    const float* W_val   = (const float*)d_in[9];
    const float* b_val   = (const float*)d_in[10];
    const float* W_out   = (const float*)d_in[11];
    const float* b_out   = (const float*)d_in[12];
    float* out = (float*)d_out;

    __half *w16, *q16, *a16, *v16, *mid16;
    float *voa, *boa;
    cudaGetSymbolAddress((void**)&w16, g_W16);
    cudaGetSymbolAddress((void**)&q16, g_q16);
    cudaGetSymbolAddress((void**)&a16, g_a16);
    cudaGetSymbolAddress((void**)&v16, g_v16);
    cudaGetSymbolAddress((void**)&mid16, g_mid16);
    cudaGetSymbolAddress((void**)&voa, g_offattn);
    cudaGetSymbolAddress((void**)&boa, g_bias_oa);

    static bool init_done = false;
    static cudaStream_t s2;
    static cudaEvent_t evPrep, evVal;
    if (!init_done) {
        cudaFuncSetAttribute((const void*)gemm_f16_kernel<float, false>,
                             cudaFuncAttributeMaxDynamicSharedMemorySize, GEMM_SMEM);
        cudaFuncSetAttribute((const void*)gemm_f16_kernel<__half, true>,
                             cudaFuncAttributeMaxDynamicSharedMemorySize, GEMM_SMEM);
        cudaStreamCreateWithFlags(&s2, cudaStreamNonBlocking);
        cudaEventCreateWithFlags(&evPrep, cudaEventDisableTiming);
        cudaEventCreateWithFlags(&evVal, cudaEventDisableTiming);
        init_done = true;
    }

    // 0) fused prep (vectorized)
    prep_kernel<<<(PREP_THREADS + 255) / 256, 256>>>(
        (const float4*)value, (const float4*)query, (const float4*)qpos,
        W_val, W_off, W_attn, W_out, b_off, b_attn);

    // fork: value-projection chain on s2
    cudaEventRecord(evPrep, 0);
    cudaStreamWaitEvent(s2, evPrep, 0);

    // 1a) [s2] v = value @ W_val + b_val -> fp16 in [b][h][pos][d] layout
    {
        int M = BSZ * LEN_VAL, N = EDIM;
        dim3 grid(N / 64, (M + 127) / 128);
        gemm_f16_kernel<__half, true><<<grid, 256, GEMM_SMEM, s2>>>(
            a16, w16 + WOFF_VAL, b_val, v16, M, N);
    }
    cudaEventRecord(evVal, s2);

    // 1b) [default] [off|attn] = q @ W_oa + b_oa (N = 768)
    {
        int M = BSZ * NQ, N = NOA;
        dim3 grid(N / 64, (M + 127) / 128);
        gemm_f16_kernel<float, false><<<grid, 256, GEMM_SMEM>>>(
            q16, w16 + WOFF_OA, boa, voa, M, N);
    }

    // join
    cudaStreamWaitEvent(0, evVal, 0);

    // 2) deformable sampling -> g_mid16
    {
        int groups = BSZ * NQ * NH;              // 160000
        sample_kernel<<<groups / 8, 256>>>(refpts);
    }
    // 3) out = mid @ W_out + b_out
    {
        int M = BSZ * NQ, N = EDIM;
        dim3 grid(N / 64, (M + 127) / 128);
        gemm_f16_kernel<float, false><<<grid, 256, GEMM_SMEM>>>(
            mid16, w16 + WOFF_OUT, b_out, out, M, N);
    }
}